// round 12
// baseline (speedup 1.0000x reference)
#include <cuda_runtime.h>
#include <cuda_fp16.h>
#include <math_constants.h>

#define Bb 4
#define Cc 64
#define C2c 32
#define Nn 1024
#define Vv 20
#define Pp (Bb*Nn*Vv)          // 81920 points
#define NVv (Nn*Vv)            // 20480
#define BNb (Bb*Nn)            // 4096 tiles
#define OUTSZ (Bb*Cc*Nn*Vv)    // 5242880
#define EPSc 1e-5f
#define NTHR 256
#define USTR 1304              // k5 smem row stride in halves

// -------- scratch (device globals; no allocation allowed) --------
__device__ float    g_xm[C2c*Pp];     // masked embed pre-BN, layout [c2][p]
__device__ __half   g_uh[OUTSZ];      // (u + T) fp16, TILE-MAJOR: [tile][o][v]
__device__ float    g_part[320*2];    // embed stat partials [unit][{s,q}]
__device__ float    g_cst[320];       // conv: S1,S2,S3,S4,Cx each [64]

// -------- f32x2 helpers --------
__device__ __forceinline__ unsigned long long dup2(float x) {
    unsigned long long r;
    asm("mov.b64 %0, {%1, %1};" : "=l"(r) : "f"(x));
    return r;
}
__device__ __forceinline__ void fma2(unsigned long long& d, unsigned long long a, unsigned long long b) {
    asm("fma.rn.f32x2 %0, %1, %2, %0;" : "+l"(d) : "l"(a), "l"(b));
}
__device__ __forceinline__ float2 unpk2(unsigned long long v) {
    float2 r;
    asm("mov.b64 {%0, %1}, %2;" : "=f"(r.x), "=f"(r.y) : "l"(v));
    return r;
}

// ==================================================================
// K1: embed GEMM, o-split 2-way. 640 blocks x 256 threads.
// Block (pb, h): point p = pb*256+tid, outputs j-pairs [h*8, h*8+8)
// (i.e. 16 of 32 channels). Halves instr/warp, doubles warps/SM.
// ==================================================================
__global__ void __launch_bounds__(NTHR) k1_embed(
    const float* __restrict__ feats, const float* __restrict__ mask,
    const float* __restrict__ wE,    const float* __restrict__ bE)
{
    __shared__ __align__(16) float wsh[Cc*16];       // [c][16]: this half's o
    int tid = threadIdx.x;
    int bid = blockIdx.x;
    int h   = bid & 1;                               // o-half
    int pb  = bid >> 1;                              // point block

    for (int j = tid; j < Cc*16; j += NTHR) {
        int c = j >> 4, oo = j & 15;                 // oo = local o index
        int o = h*16 + oo;
        wsh[j] = wE[o*64 + c];
    }
    if (bid == 0)
        for (int i = tid; i < 320; i += NTHR) g_cst[i] = 0.f;
    __syncthreads();

    const ulonglong2* wsh4 = (const ulonglong2*)wsh; // 4 per c
    int p  = pb * NTHR + tid;                        // exact: 320*256 = 81920
    int b  = p / NVv;
    int nv = p - b * NVv;
    const float* fptr = feats + (size_t)b * Cc * NVv + nv;

    unsigned long long acc[8];
    #pragma unroll
    for (int j = 0; j < 8; ++j) acc[j] = 0ULL;

    #pragma unroll 8
    for (int c = 0; c < Cc; ++c) {
        unsigned long long fa = dup2(__ldg(fptr + c * NVv));
        #pragma unroll
        for (int j = 0; j < 4; ++j) {
            ulonglong2 w = wsh4[c*4 + j];
            fma2(acc[2*j],   w.x, fa);
            fma2(acc[2*j+1], w.y, fa);
        }
    }

    float m = __ldg(mask + p);
    #pragma unroll
    for (int j = 0; j < 8; ++j) {
        float2 v = unpk2(acc[j]);
        int o0 = h*16 + 2*j, o1 = o0 + 1;
        g_xm[(size_t)o0*Pp + p] = (v.x + __ldg(bE + o0)) * m;
        g_xm[(size_t)o1*Pp + p] = (v.y + __ldg(bE + o1)) * m;
    }
}

// ==================================================================
// K2: embed stats (atomic-free). 320 blocks = exactly 1 unit/block.
// ==================================================================
__global__ void __launch_bounds__(NTHR) k2_stats()
{
    __shared__ float ss[8], qq[8];
    int tid = threadIdx.x;
    int u = blockIdx.x;                               // 320 units exactly
    int c2 = u / 10, chunk = u - c2 * 10;
    const float4* src = (const float4*)(g_xm + (size_t)c2 * Pp + chunk * 8192);

    float4 v[8];
    #pragma unroll
    for (int k = 0; k < 8; ++k) v[k] = __ldg(src + tid + k * 256);
    float s = 0.f, q = 0.f;
    #pragma unroll
    for (int k = 0; k < 8; ++k) {
        s += v[k].x + v[k].y + v[k].z + v[k].w;
        q += v[k].x*v[k].x + v[k].y*v[k].y + v[k].z*v[k].z + v[k].w*v[k].w;
    }
    #pragma unroll
    for (int d = 16; d; d >>= 1) {
        s += __shfl_xor_sync(0xffffffffu, s, d);
        q += __shfl_xor_sync(0xffffffffu, q, d);
    }
    int wid = tid >> 5;
    if ((tid & 31) == 0) { ss[wid] = s; qq[wid] = q; }
    __syncthreads();
    if (tid == 0) {
        float S = 0.f, Q = 0.f;
        #pragma unroll
        for (int w = 0; w < 8; ++w) { S += ss[w]; Q += qq[w]; }
        g_part[u*2]     = S;
        g_part[u*2 + 1] = Q;
    }
}

// ==================================================================
// K3: u/t GEMV + conv stats + fused T (standalone — natural occupancy).
// 1024 blocks x 128 threads; each block 4 tiles, 2 concurrent halves.
// ==================================================================
__global__ void __launch_bounds__(128) k3_conv(
    const float* __restrict__ mask, const float* __restrict__ wC,
    const float* __restrict__ gE, const float* __restrict__ beE)
{
    __shared__ float wshU[64*33];                  // W1-W2, row stride 33
    __shared__ float wshT[64*33];                  // W2
    __shared__ __align__(16) float xs[2][C2c*Vv];  // per-half x tile
    __shared__ float bnA[64];

    int tid  = threadIdx.x;
    int half = tid >> 6;
    int o    = tid & 63;

    for (int j = tid; j < 64*32; j += 128) {
        int oo = j >> 5, c2 = j & 31;
        float w2 = wC[oo*64 + 32 + c2];
        wshT[oo*33 + c2] = w2;
        wshU[oo*33 + c2] = wC[oo*64 + c2] - w2;
    }
    if (tid < 32) {                                // finalize embed BN
        float s = 0.f, q = 0.f;
        #pragma unroll
        for (int ch = 0; ch < 10; ++ch) {
            s += g_part[(tid*10 + ch)*2];
            q += g_part[(tid*10 + ch)*2 + 1];
        }
        float inv  = 1.f / (float)Pp;
        float mean = s * inv;
        float var  = q * inv - mean * mean;
        float sc   = rsqrtf(var + EPSc) * __ldg(gE + tid);
        bnA[tid]      = sc;
        bnA[32 + tid] = __ldg(beE + tid) - mean * sc;
    }

    float S1 = 0.f, S2 = 0.f, S3 = 0.f, S4 = 0.f, CX = 0.f;

    #pragma unroll
    for (int it2 = 0; it2 < 2; ++it2) {
        __syncthreads();
        #pragma unroll
        for (int k = 0; k < 10; ++k) {
            int i  = tid + k * 128;
            int h  = i / 640;
            int j  = i - h * 640;
            int c2 = j / Vv, v = j - c2 * Vv;
            int tId = blockIdx.x * 4 + it2 * 2 + h;
            int p  = tId * Vv + v;
            float val = g_xm[(size_t)c2 * Pp + p];
            xs[h][c2*Vv + v] =
                fmaxf(fmaf(val, bnA[c2], bnA[32 + c2]), 0.f) * __ldg(mask + p);
        }
        __syncthreads();

        int tileId = blockIdx.x * 4 + it2 * 2 + half;
        const ulonglong2* xv = (const ulonglong2*)xs[half];

        unsigned long long ua[10], ta[10];
        #pragma unroll
        for (int q = 0; q < 10; ++q) { ua[q] = 0ULL; ta[q] = 0ULL; }

        #pragma unroll
        for (int c2 = 0; c2 < 32; ++c2) {
            unsigned long long wu = dup2(wshU[o*33 + c2]);   // conflict-free
            unsigned long long wt = dup2(wshT[o*33 + c2]);
            #pragma unroll
            for (int q = 0; q < 5; ++q) {
                ulonglong2 x = xv[c2*5 + q];
                fma2(ua[2*q],   wu, x.x);
                fma2(ua[2*q+1], wu, x.y);
                fma2(ta[2*q],   wt, x.x);
                fma2(ta[2*q+1], wt, x.y);
            }
        }

        float a[20], tt[20];
        #pragma unroll
        for (int q = 0; q < 10; ++q) {
            float2 v1 = unpk2(ua[q]); a[2*q]  = v1.x; a[2*q+1]  = v1.y;
            float2 v2 = unpk2(ta[q]); tt[2*q] = v2.x; tt[2*q+1] = v2.y;
        }

        float su = 0.f, qu = 0.f, st = 0.f, qt = 0.f, mxt = -CUDART_INF_F;
        #pragma unroll
        for (int v = 0; v < 20; ++v) {
            su += a[v];  qu += a[v]*a[v];
            st += tt[v]; qt += tt[v]*tt[v];
            mxt = fmaxf(mxt, tt[v]);
        }

        // store (u + T) fp16, tile-major, contiguous 40B per thread
        union { uint2 u2; __half2 h2[2]; } pk;
        uint2* up = (uint2*)g_uh + ((size_t)tileId * 64 + o) * 5;
        #pragma unroll
        for (int k = 0; k < 5; ++k) {
            pk.h2[0] = __floats2half2_rn(a[4*k]   + mxt, a[4*k+1] + mxt);
            pk.h2[1] = __floats2half2_rn(a[4*k+2] + mxt, a[4*k+3] + mxt);
            up[k] = pk.u2;
        }

        S1 += su; S2 += qu; S3 += st; S4 += qt; CX += su * st;
    }

    atomicAdd(&g_cst[o],       S1);
    atomicAdd(&g_cst[64  + o], S2);
    atomicAdd(&g_cst[128 + o], S3);
    atomicAdd(&g_cst[192 + o], S4);
    atomicAdd(&g_cst[256 + o], CX);
}

// ==================================================================
// K5: epilogue with smem transpose (standalone). 1024 blocks x 256.
// out = feats + mask * relu(w * scale + shift),  w = u + T (fp16)
// ==================================================================
__global__ void __launch_bounds__(NTHR) k5_out(
    const float* __restrict__ feats, const float* __restrict__ mask,
    const float* __restrict__ gC, const float* __restrict__ beC,
    float* __restrict__ out)
{
    __shared__ __align__(16) __half us[4 * USTR];   // 10432 B
    __shared__ float2 bnsm[64];

    int tid = threadIdx.x;
    int T0  = blockIdx.x * 4;                 // 1024 blocks
    int b   = T0 >> 10, n0 = T0 & 1023;

    // stage u chunk: 5120 halves = 640 uint4, coalesced
    const uint4* src = (const uint4*)(g_uh + (size_t)T0 * 1280);
    {
        int g0 = tid,       n_0 = g0 / 160;
        int g1 = tid + 256, n_1 = g1 / 160;
        uint4 v0 = __ldg(src + g0);
        uint4 v1 = __ldg(src + g1);
        uint4 v2;
        int g2 = tid + 512, n_2 = g2 / 160;
        if (tid < 128) v2 = __ldg(src + g2);
        ((uint4*)us)[n_0 * (USTR/8) + (g0 - n_0*160)] = v0;
        ((uint4*)us)[n_1 * (USTR/8) + (g1 - n_1*160)] = v1;
        if (tid < 128)
            ((uint4*)us)[n_2 * (USTR/8) + (g2 - n_2*160)] = v2;
    }

    if (tid < 64) {                           // conv-BN finalize
        int o = tid;
        float Sa = g_cst[o], Sb = g_cst[64+o], Sc = g_cst[128+o],
              Sd = g_cst[192+o], Cx = g_cst[256+o];
        const float invM = 1.f / ((float)Bb * Nn * Vv * Vv);
        float mean = (float)Vv * (Sa + Sc) * invM;
        float ey2  = ((float)Vv * (Sb + Sd) + 2.f * Cx) * invM;
        float sc   = rsqrtf(ey2 - mean * mean + EPSc) * __ldg(gC + o);
        bnsm[o] = make_float2(sc, __ldg(beC + o) - mean * sc);
    }
    __syncthreads();

    // 1280 float4 outputs per block, 5 per thread
    #pragma unroll
    for (int k = 0; k < 5; ++k) {
        int q = tid + k * 256;
        int o = q / 20;
        int r = q - 20 * o;
        int n = r / 5;
        int j = r - 5 * n;

        uint2 raw = ((const uint2*)us)[n * (USTR/4) + o * 5 + j];
        float2 w0 = __half22float2(((const __half2*)&raw)[0]);
        float2 w1 = __half22float2(((const __half2*)&raw)[1]);

        float2 bn = bnsm[o];
        float sc = bn.x, sh = bn.y;

        size_t o4 = ((size_t)(b*64 + o) * 1024 + n0 + n) * 5 + j;
        float4 fe = __ldg((const float4*)feats + o4);
        float4 mk = __ldg((const float4*)mask + ((size_t)b * 1024 + n0 + n) * 5 + j);

        float4 rr;
        rr.x = fe.x + mk.x * fmaxf(fmaf(w0.x, sc, sh), 0.f);
        rr.y = fe.y + mk.y * fmaxf(fmaf(w0.y, sc, sh), 0.f);
        rr.z = fe.z + mk.z * fmaxf(fmaf(w1.x, sc, sh), 0.f);
        rr.w = fe.w + mk.w * fmaxf(fmaf(w1.y, sc, sh), 0.f);
        ((float4*)out)[o4] = rr;
    }
}

// ==================== launch ====================
extern "C" void kernel_launch(void* const* d_in, const int* in_sizes, int n_in,
                              void* d_out, int out_size) {
    const float* feats = (const float*)d_in[0];
    const float* mask  = (const float*)d_in[1];
    const float* wE    = (const float*)d_in[2];
    const float* bE    = (const float*)d_in[3];
    const float* gE    = (const float*)d_in[4];
    const float* beE   = (const float*)d_in[5];
    const float* wC    = (const float*)d_in[6];
    const float* gC    = (const float*)d_in[7];
    const float* beC   = (const float*)d_in[8];
    float* out = (float*)d_out;

    k1_embed<<<640, NTHR>>>(feats, mask, wE, bE);      // o-split 2-way
    k2_stats<<<320, NTHR>>>();
    k3_conv<<<BNb/4, 128>>>(mask, wC, gE, beE);        // 1024 blocks
    k5_out<<<BNb/4, NTHR>>>(feats, mask, gC, beC, out);// 1024 blocks
}

// round 13
// speedup vs baseline: 1.1373x; 1.1373x over previous
#include <cuda_runtime.h>
#include <cuda_fp16.h>
#include <math_constants.h>

#define Bb 4
#define Cc 64
#define C2c 32
#define Nn 1024
#define Vv 20
#define Pp (Bb*Nn*Vv)          // 81920 points
#define NVv (Nn*Vv)            // 20480
#define BNb (Bb*Nn)            // 4096 tiles
#define OUTSZ (Bb*Cc*Nn*Vv)    // 5242880
#define EPSc 1e-5f
#define NTHR 256
#define NBLK_B 296             // kB: 2 blocks/SM x 148 SMs — full wave
#define USTR 1304              // phase-4 smem row stride in halves

// -------- scratch (device globals; no allocation allowed) --------
__device__ float    g_xm[C2c*Pp];     // masked embed pre-BN, layout [c2][p]
__device__ __half   g_uh[OUTSZ];      // (u + T) fp16, TILE-MAJOR: [tile][o][v]
__device__ float    g_part[320*2];    // embed stat partials [unit][{s,q}]
__device__ float    g_cst[320];       // conv: S1,S2,S3,S4,Cx each [64]
__device__ unsigned g_ctr;            // monotonic barrier counter (zero-init)

// -------- f32x2 helpers --------
__device__ __forceinline__ unsigned long long dup2(float x) {
    unsigned long long r;
    asm("mov.b64 %0, {%1, %1};" : "=l"(r) : "f"(x));
    return r;
}
__device__ __forceinline__ void fma2(unsigned long long& d, unsigned long long a, unsigned long long b) {
    asm("fma.rn.f32x2 %0, %1, %2, %0;" : "+l"(d) : "l"(a), "l"(b));
}
__device__ __forceinline__ float2 unpk2(unsigned long long v) {
    float2 r;
    asm("mov.b64 {%0, %1}, %2;" : "=f"(r.x), "=f"(r.y) : "l"(v));
    return r;
}

// -------- monotonic device-wide barrier (never reset; replay-safe) --------
// At kernel start g_ctr is a multiple of NBLK_B (stream ordering guarantees
// all prior launches completed their increments). Called twice per kB launch:
// targets k+296, k+592 — both multiples, so replays stay aligned.
__device__ __forceinline__ void gbarM(unsigned nblk) {
    __syncthreads();
    if (threadIdx.x == 0) {
        __threadfence();                              // publish phase data
        unsigned prev   = atomicAdd(&g_ctr, 1);
        unsigned target = prev - (prev % nblk) + nblk;
        while (*((volatile unsigned*)&g_ctr) < target) { }
        __threadfence();                              // acquire phase data
    }
    __syncthreads();
}

// ==================================================================
// K1: embed GEMM, o-split 2-way. 640 blocks x 256 threads.
// Block (pb, h): point p = pb*256+tid, outputs 16 of 32 channels.
// ==================================================================
__global__ void __launch_bounds__(NTHR) k1_embed(
    const float* __restrict__ feats, const float* __restrict__ mask,
    const float* __restrict__ wE,    const float* __restrict__ bE)
{
    __shared__ __align__(16) float wsh[Cc*16];       // [c][16]: this half's o
    int tid = threadIdx.x;
    int bid = blockIdx.x;
    int h   = bid & 1;                               // o-half
    int pb  = bid >> 1;                              // point block

    for (int j = tid; j < Cc*16; j += NTHR) {
        int c = j >> 4, oo = j & 15;
        int o = h*16 + oo;
        wsh[j] = wE[o*64 + c];
    }
    if (bid == 0)
        for (int i = tid; i < 320; i += NTHR) g_cst[i] = 0.f;
    __syncthreads();

    const ulonglong2* wsh4 = (const ulonglong2*)wsh; // 4 per c
    int p  = pb * NTHR + tid;                        // exact: 320*256 = 81920
    int b  = p / NVv;
    int nv = p - b * NVv;
    const float* fptr = feats + (size_t)b * Cc * NVv + nv;

    unsigned long long acc[8];
    #pragma unroll
    for (int j = 0; j < 8; ++j) acc[j] = 0ULL;

    #pragma unroll 8
    for (int c = 0; c < Cc; ++c) {
        unsigned long long fa = dup2(__ldg(fptr + c * NVv));
        #pragma unroll
        for (int j = 0; j < 4; ++j) {
            ulonglong2 w = wsh4[c*4 + j];
            fma2(acc[2*j],   w.x, fa);
            fma2(acc[2*j+1], w.y, fa);
        }
    }

    float m = __ldg(mask + p);
    #pragma unroll
    for (int j = 0; j < 8; ++j) {
        float2 v = unpk2(acc[j]);
        int o0 = h*16 + 2*j, o1 = o0 + 1;
        g_xm[(size_t)o0*Pp + p] = (v.x + __ldg(bE + o0)) * m;
        g_xm[(size_t)o1*Pp + p] = (v.y + __ldg(bE + o1)) * m;
    }
}

// ==================================================================
// Kernel B: Phase 0 (embed stats) + barrier + Phase 3 (u/t GEMV + conv
// stats + fused T) + barrier + Phase 4 (epilogue).
// 296 blocks x 256 threads, 2/SM guaranteed.
// ==================================================================
union SmemB {
    struct { float ss[8], qq[8]; } p2;
    struct { float wshU[64*33], wshT[64*33];
             float xs[4][C2c*Vv]; float bnA[64]; } p3;             // 27.4 KB
    struct { __half us[4*USTR]; float2 bnsm[64]; } p5;             // 10.9 KB
};

__global__ void __launch_bounds__(NTHR, 2) kB(
    const float* __restrict__ feats, const float* __restrict__ mask,
    const float* __restrict__ gE,    const float* __restrict__ beE,
    const float* __restrict__ wC,    const float* __restrict__ gC,
    const float* __restrict__ beC,   float* __restrict__ out)
{
    __shared__ __align__(16) SmemB sm;
    int tid = threadIdx.x;
    int bid = blockIdx.x;

    // ---------- Phase 0: embed stats (atomic-free; 320 units) ----------
    #pragma unroll
    for (int rep = 0; rep < 2; ++rep) {
        int u = bid + rep * NBLK_B;
        if (u >= 320) break;
        __syncthreads();
        int c2 = u / 10, chunk = u - c2 * 10;
        const float4* src = (const float4*)(g_xm + (size_t)c2 * Pp + chunk * 8192);

        float4 v[8];
        #pragma unroll
        for (int k = 0; k < 8; ++k) v[k] = __ldg(src + tid + k * 256);
        float s = 0.f, q = 0.f;
        #pragma unroll
        for (int k = 0; k < 8; ++k) {
            s += v[k].x + v[k].y + v[k].z + v[k].w;
            q += v[k].x*v[k].x + v[k].y*v[k].y + v[k].z*v[k].z + v[k].w*v[k].w;
        }
        #pragma unroll
        for (int d = 16; d; d >>= 1) {
            s += __shfl_xor_sync(0xffffffffu, s, d);
            q += __shfl_xor_sync(0xffffffffu, q, d);
        }
        int wid = tid >> 5;
        if ((tid & 31) == 0) { sm.p2.ss[wid] = s; sm.p2.qq[wid] = q; }
        __syncthreads();
        if (tid == 0) {
            float S = 0.f, Q = 0.f;
            #pragma unroll
            for (int w = 0; w < 8; ++w) { S += sm.p2.ss[w]; Q += sm.p2.qq[w]; }
            g_part[u*2]     = S;
            g_part[u*2 + 1] = Q;
        }
    }
    gbarM(NBLK_B);

    // ---------- Phase 3 ----------
    {
        for (int j = tid; j < 64*32; j += NTHR) {
            int oo = j >> 5, c2 = j & 31;
            float w2 = wC[oo*64 + 32 + c2];
            sm.p3.wshT[oo*33 + c2] = w2;
            sm.p3.wshU[oo*33 + c2] = wC[oo*64 + c2] - w2;
        }
        if (tid < 32) {                                // finalize embed BN
            float s = 0.f, q = 0.f;
            #pragma unroll
            for (int ch = 0; ch < 10; ++ch) {
                s += g_part[(tid*10 + ch)*2];
                q += g_part[(tid*10 + ch)*2 + 1];
            }
            float inv  = 1.f / (float)Pp;
            float mean = s * inv;
            float var  = q * inv - mean * mean;
            float sc   = rsqrtf(var + EPSc) * __ldg(gE + tid);
            sm.p3.bnA[tid]      = sc;
            sm.p3.bnA[32 + tid] = __ldg(beE + tid) - mean * sc;
        }

        int quarter = tid >> 6;
        int o       = tid & 63;
        float S1 = 0.f, S2 = 0.f, S3 = 0.f, S4 = 0.f, CX = 0.f;

        #pragma unroll
        for (int it = 0; it < 4; ++it) {
            __syncthreads();
            #pragma unroll
            for (int k = 0; k < 10; ++k) {
                int i  = tid + k * NTHR;
                int h  = i / 640;
                int j  = i - h * 640;
                int c2 = j / Vv, v = j - c2 * Vv;
                int tId = bid * 4 + h + it * (NBLK_B*4);
                float x = 0.f;
                if (tId < BNb) {
                    int p = tId * Vv + v;
                    float val = g_xm[(size_t)c2 * Pp + p];
                    x = fmaxf(fmaf(val, sm.p3.bnA[c2], sm.p3.bnA[32 + c2]), 0.f)
                        * __ldg(mask + p);
                }
                sm.p3.xs[h][c2*Vv + v] = x;
            }
            __syncthreads();

            int tileId = bid * 4 + quarter + it * (NBLK_B*4);
            if (tileId < BNb) {
                const ulonglong2* xv = (const ulonglong2*)sm.p3.xs[quarter];

                unsigned long long ua[10], ta[10];
                #pragma unroll
                for (int q = 0; q < 10; ++q) { ua[q] = 0ULL; ta[q] = 0ULL; }

                #pragma unroll
                for (int c2 = 0; c2 < 32; ++c2) {
                    unsigned long long wu = dup2(sm.p3.wshU[o*33 + c2]);
                    unsigned long long wt = dup2(sm.p3.wshT[o*33 + c2]);
                    #pragma unroll
                    for (int q = 0; q < 5; ++q) {
                        ulonglong2 x = xv[c2*5 + q];
                        fma2(ua[2*q],   wu, x.x);
                        fma2(ua[2*q+1], wu, x.y);
                        fma2(ta[2*q],   wt, x.x);
                        fma2(ta[2*q+1], wt, x.y);
                    }
                }

                float a[20], tt[20];
                #pragma unroll
                for (int q = 0; q < 10; ++q) {
                    float2 v1 = unpk2(ua[q]); a[2*q]  = v1.x; a[2*q+1]  = v1.y;
                    float2 v2 = unpk2(ta[q]); tt[2*q] = v2.x; tt[2*q+1] = v2.y;
                }

                float su = 0.f, qu = 0.f, st = 0.f, qt = 0.f, mxt = -CUDART_INF_F;
                #pragma unroll
                for (int v = 0; v < 20; ++v) {
                    su += a[v];  qu += a[v]*a[v];
                    st += tt[v]; qt += tt[v]*tt[v];
                    mxt = fmaxf(mxt, tt[v]);
                }

                union { uint2 u2; __half2 h2[2]; } pk;
                uint2* up = (uint2*)g_uh + ((size_t)tileId * 64 + o) * 5;
                #pragma unroll
                for (int k = 0; k < 5; ++k) {
                    pk.h2[0] = __floats2half2_rn(a[4*k]   + mxt, a[4*k+1] + mxt);
                    pk.h2[1] = __floats2half2_rn(a[4*k+2] + mxt, a[4*k+3] + mxt);
                    up[k] = pk.u2;
                }
                S1 += su; S2 += qu; S3 += st; S4 += qt; CX += su * st;
            }
        }

        atomicAdd(&g_cst[o],       S1);
        atomicAdd(&g_cst[64  + o], S2);
        atomicAdd(&g_cst[128 + o], S3);
        atomicAdd(&g_cst[192 + o], S4);
        atomicAdd(&g_cst[256 + o], CX);
    }
    gbarM(NBLK_B);

    // ---------- Phase 4: epilogue ----------
    {
        if (tid < 64) {                                // conv-BN finalize
            int o = tid;
            float Sa = g_cst[o], Sb = g_cst[64+o], Sc = g_cst[128+o],
                  Sd = g_cst[192+o], Cx = g_cst[256+o];
            const float invM = 1.f / ((float)Bb * Nn * Vv * Vv);
            float mean = (float)Vv * (Sa + Sc) * invM;
            float ey2  = ((float)Vv * (Sb + Sd) + 2.f * Cx) * invM;
            float sc   = rsqrtf(ey2 - mean * mean + EPSc) * __ldg(gC + o);
            sm.p5.bnsm[o] = make_float2(sc, __ldg(beC + o) - mean * sc);
        }

        #pragma unroll
        for (int it = 0; it < 4; ++it) {
            int g = bid + it * NBLK_B;
            if (g >= BNb/4) break;
            __syncthreads();                           // us reuse / bnsm ready
            int T0 = g * 4;
            int b  = T0 >> 10, n0 = T0 & 1023;

            const uint4* src = (const uint4*)(g_uh + (size_t)T0 * 1280);
            {
                int g0 = tid,       n_0 = g0 / 160;
                int g1 = tid + 256, n_1 = g1 / 160;
                uint4 v0 = __ldg(src + g0);
                uint4 v1 = __ldg(src + g1);
                uint4 v2;
                int g2 = tid + 512, n_2 = g2 / 160;
                if (tid < 128) v2 = __ldg(src + g2);
                ((uint4*)sm.p5.us)[n_0 * (USTR/8) + (g0 - n_0*160)] = v0;
                ((uint4*)sm.p5.us)[n_1 * (USTR/8) + (g1 - n_1*160)] = v1;
                if (tid < 128)
                    ((uint4*)sm.p5.us)[n_2 * (USTR/8) + (g2 - n_2*160)] = v2;
            }
            __syncthreads();

            #pragma unroll
            for (int k = 0; k < 5; ++k) {
                int q = tid + k * 256;
                int o = q / 20;
                int r = q - 20 * o;
                int n = r / 5;
                int j = r - 5 * n;

                uint2 raw = ((const uint2*)sm.p5.us)[n * (USTR/4) + o * 5 + j];
                float2 w0 = __half22float2(((const __half2*)&raw)[0]);
                float2 w1 = __half22float2(((const __half2*)&raw)[1]);

                float2 bn = sm.p5.bnsm[o];
                float sc = bn.x, sh = bn.y;

                size_t o4 = ((size_t)(b*64 + o) * 1024 + n0 + n) * 5 + j;
                float4 fe = __ldg((const float4*)feats + o4);
                float4 mk = __ldg((const float4*)mask + ((size_t)b * 1024 + n0 + n) * 5 + j);

                float4 rr;
                rr.x = fe.x + mk.x * fmaxf(fmaf(w0.x, sc, sh), 0.f);
                rr.y = fe.y + mk.y * fmaxf(fmaf(w0.y, sc, sh), 0.f);
                rr.z = fe.z + mk.z * fmaxf(fmaf(w1.x, sc, sh), 0.f);
                rr.w = fe.w + mk.w * fmaxf(fmaf(w1.y, sc, sh), 0.f);
                ((float4*)out)[o4] = rr;
            }
        }
    }
}

// ==================== launch ====================
extern "C" void kernel_launch(void* const* d_in, const int* in_sizes, int n_in,
                              void* d_out, int out_size) {
    const float* feats = (const float*)d_in[0];
    const float* mask  = (const float*)d_in[1];
    const float* wE    = (const float*)d_in[2];
    const float* bE    = (const float*)d_in[3];
    const float* gE    = (const float*)d_in[4];
    const float* beE   = (const float*)d_in[5];
    const float* wC    = (const float*)d_in[6];
    const float* gC    = (const float*)d_in[7];
    const float* beC   = (const float*)d_in[8];
    float* out = (float*)d_out;

    k1_embed<<<640, NTHR>>>(feats, mask, wE, bE);      // o-split 2-way
    kB<<<NBLK_B, NTHR>>>(feats, mask, gE, beE, wC, gC, beC, out);
}